// round 5
// baseline (speedup 1.0000x reference)
#include <cuda_runtime.h>
#include <cuda_fp16.h>
#include <cstdint>

#define D 128
#define MAX_N 100000
#define MAX_E 3200000
#define TM 64                 // GEMM row tile

// ---------------------------------------------------------------------------
// Static device scratch
// ---------------------------------------------------------------------------
__device__ int    g_is64;               // 1 if edge_index is int64, 0 if int32
__device__ int    g_cnt [MAX_N];        // in-degree histogram (no self loops)
__device__ int    g_ptr [MAX_N];        // CSR row starts
__device__ int    g_fill[MAX_N];        // fill cursors
__device__ int    g_srcs[MAX_E];        // src ids bucketed by dst
__device__ float  g_dis [MAX_N];        // deg^-1/2 (deg includes self loop)
__device__ __half g_hp  [(size_t)MAX_N * D];   // (x @ W^T) * dis[row], fp16

// ---------------------------------------------------------------------------
// 0. dtype detect: OR odd 32-bit words of the first 2048 "int64 slots".
// ---------------------------------------------------------------------------
__global__ void detect_kernel(const int* __restrict__ p) {
    __shared__ int any;
    if (threadIdx.x == 0) any = 0;
    __syncthreads();
    int v = 0;
    for (int i = threadIdx.x; i < 2048; i += blockDim.x) v |= p[2 * i + 1];
    if (v) atomicOr(&any, 1);
    __syncthreads();
    if (threadIdx.x == 0) g_is64 = (any == 0) ? 1 : 0;
}

// ---------------------------------------------------------------------------
// 1. zero histogram
// ---------------------------------------------------------------------------
__global__ void zero_cnt_kernel(int n) {
    int i = blockIdx.x * blockDim.x + threadIdx.x;
    if (i < n) g_cnt[i] = 0;
}

// ---------------------------------------------------------------------------
// 2. histogram over dst (int4-vectorized int32 fast path)
// ---------------------------------------------------------------------------
__global__ void hist_kernel(const int* __restrict__ p, int e, int n) {
    int gid = blockIdx.x * blockDim.x + threadIdx.x;
    int stride = gridDim.x * blockDim.x;
    if (!g_is64) {
        const int4* d4 = (const int4*)(p + e);   // dst block, 16B-aligned (e mult of 4)
        int e4 = e >> 2;
        for (int i = gid; i < e4; i += stride) {
            int4 v = d4[i];
            if ((unsigned)v.x < (unsigned)n) atomicAdd(&g_cnt[v.x], 1);
            if ((unsigned)v.y < (unsigned)n) atomicAdd(&g_cnt[v.y], 1);
            if ((unsigned)v.z < (unsigned)n) atomicAdd(&g_cnt[v.z], 1);
            if ((unsigned)v.w < (unsigned)n) atomicAdd(&g_cnt[v.w], 1);
        }
        // tail (e not multiple of 4)
        if (gid < (e & 3)) {
            int d = p[(size_t)e + (e & ~3) + gid];
            if ((unsigned)d < (unsigned)n) atomicAdd(&g_cnt[d], 1);
        }
    } else {
        for (int i = gid; i < e; i += stride) {
            int d = p[2 * ((size_t)e + i)];
            if ((unsigned)d < (unsigned)n) atomicAdd(&g_cnt[d], 1);
        }
    }
}

// ---------------------------------------------------------------------------
// 3. fused scan (single block, 1024 threads): ptr/fill/dis from cnt
// ---------------------------------------------------------------------------
__global__ __launch_bounds__(1024) void scan_fused_kernel(int n) {
    __shared__ int sh[1024];
    const int t = threadIdx.x;
    const int chunk = (n + 1023) >> 10;
    const int b = t * chunk, eend = min(b + chunk, n);

    int s = 0;
    for (int i = b; i < eend; i++) s += g_cnt[i];
    sh[t] = s;
    __syncthreads();
    for (int off = 1; off < 1024; off <<= 1) {
        int add = (t >= off) ? sh[t - off] : 0;
        __syncthreads();
        sh[t] += add;
        __syncthreads();
    }
    int run = sh[t] - s;   // exclusive prefix
    for (int i = b; i < eend; i++) {
        g_ptr[i] = run;
        g_fill[i] = run;
        int c = g_cnt[i];
        g_dis[i] = rsqrtf((float)(c + 1));   // +1 self loop
        run += c;
    }
}

// ---------------------------------------------------------------------------
// 4. fill: bucket src ids by dst (int4-vectorized int32 fast path)
// ---------------------------------------------------------------------------
__device__ __forceinline__ void fill_one(int s, int d, int n) {
    if ((unsigned)d < (unsigned)n) {
        if ((unsigned)s >= (unsigned)n) s = 0;     // defensive clamp
        int pos = atomicAdd(&g_fill[d], 1);
        if (pos < MAX_E) g_srcs[pos] = s;
    }
}

__global__ void fill_kernel(const int* __restrict__ p, int e, int n) {
    int gid = blockIdx.x * blockDim.x + threadIdx.x;
    int stride = gridDim.x * blockDim.x;
    if (!g_is64) {
        const int4* s4 = (const int4*)p;
        const int4* d4 = (const int4*)(p + e);
        int e4 = e >> 2;
        for (int i = gid; i < e4; i += stride) {
            int4 sv = s4[i];
            int4 dv = d4[i];
            fill_one(sv.x, dv.x, n);
            fill_one(sv.y, dv.y, n);
            fill_one(sv.z, dv.z, n);
            fill_one(sv.w, dv.w, n);
        }
        if (gid < (e & 3)) {
            int i = (e & ~3) + gid;
            fill_one(p[i], p[(size_t)e + i], n);
        }
    } else {
        for (int i = gid; i < e; i += stride) {
            int s = p[2 * (size_t)i];
            int d = p[2 * ((size_t)e + i)];
            fill_one(s, d, n);
        }
    }
}

// ---------------------------------------------------------------------------
// 5. GEMM: g_hp[r][c] = half( (sum_k x[r][k] * w[c][k]) * g_dis[r] )
//    256 thr, 64 rows x 128 cols per block, 8x4 register tile per thread.
// ---------------------------------------------------------------------------
__global__ __launch_bounds__(256) void gemm_kernel(
    const float* __restrict__ x, const float* __restrict__ w, int n)
{
    __shared__ float xs[TM][64];     // 16 KB
    __shared__ float wt[64][D];      // 32 KB

    const int tx = threadIdx.x & 31;
    const int ty = threadIdx.x >> 5;
    const int row0 = blockIdx.x * TM;

    float acc[8][4];
#pragma unroll
    for (int i = 0; i < 8; i++) { acc[i][0]=0.f; acc[i][1]=0.f; acc[i][2]=0.f; acc[i][3]=0.f; }

    for (int k0 = 0; k0 < D; k0 += 64) {
        for (int i = threadIdx.x; i < TM * 16; i += 256) {
            int r = i >> 4, q = i & 15;
            float4 v = make_float4(0.f, 0.f, 0.f, 0.f);
            if (row0 + r < n)
                v = ((const float4*)(x + (size_t)(row0 + r) * D + k0))[q];
            *(float4*)&xs[r][q * 4] = v;
        }
        for (int i = threadIdx.x; i < D * 16; i += 256) {
            int c = i >> 4, q = i & 15;
            float4 v = ((const float4*)(w + (size_t)c * D + k0))[q];
            wt[q * 4 + 0][c] = v.x;
            wt[q * 4 + 1][c] = v.y;
            wt[q * 4 + 2][c] = v.z;
            wt[q * 4 + 3][c] = v.w;
        }
        __syncthreads();

#pragma unroll
        for (int kk = 0; kk < 64; kk++) {
            float4 wv = *(const float4*)&wt[kk][tx * 4];
#pragma unroll
            for (int i = 0; i < 8; i++) {
                float xv = xs[ty + 8 * i][kk];
                acc[i][0] = fmaf(xv, wv.x, acc[i][0]);
                acc[i][1] = fmaf(xv, wv.y, acc[i][1]);
                acc[i][2] = fmaf(xv, wv.z, acc[i][2]);
                acc[i][3] = fmaf(xv, wv.w, acc[i][3]);
            }
        }
        __syncthreads();
    }

    uint2* hp2 = (uint2*)g_hp;    // 8B = 4 halves per lane
#pragma unroll
    for (int i = 0; i < 8; i++) {
        int r = row0 + ty + 8 * i;
        if (r < n) {
            float s = g_dis[r];
            __half2 h01 = __floats2half2_rn(acc[i][0] * s, acc[i][1] * s);
            __half2 h23 = __floats2half2_rn(acc[i][2] * s, acc[i][3] * s);
            uint2 o;
            o.x = *reinterpret_cast<unsigned*>(&h01);
            o.y = *reinterpret_cast<unsigned*>(&h23);
            hp2[(size_t)r * 32 + tx] = o;
        }
    }
}

// ---------------------------------------------------------------------------
// 6. gather-aggregate: one warp per node, fp16 gather, fp32 accumulate.
//    out[d] = dis[d] * (hp[d] + sum_{s in srcs[d]} hp[s]) + bias
// ---------------------------------------------------------------------------
__device__ __forceinline__ void acc_h4(float4& a, uint2 v) {
    __half2 h0 = *reinterpret_cast<__half2*>(&v.x);
    __half2 h1 = *reinterpret_cast<__half2*>(&v.y);
    float2 f0 = __half22float2(h0);
    float2 f1 = __half22float2(h1);
    a.x += f0.x; a.y += f0.y; a.z += f1.x; a.w += f1.y;
}

__global__ __launch_bounds__(256) void aggregate_kernel(
    const float* __restrict__ bias, float* __restrict__ out, int n)
{
    int warp = (blockIdx.x * blockDim.x + threadIdx.x) >> 5;
    int lane = threadIdx.x & 31;
    if (warp >= n) return;

    const uint2* hpv = (const uint2*)g_hp;
    int start = g_ptr[warp];
    int k = g_cnt[warp];

    float4 a0 = make_float4(0.f, 0.f, 0.f, 0.f);
    float4 a1 = make_float4(0.f, 0.f, 0.f, 0.f);
    acc_h4(a0, hpv[(size_t)warp * 32 + lane]);      // self-loop term

    int full = k & ~31;
    int j = 0;
    for (; j < full; j += 32) {
        int my = g_srcs[start + j + lane];
#pragma unroll
        for (int t = 0; t < 32; t++) {
            int s = __shfl_sync(0xFFFFFFFFu, my, t);
            uint2 v = hpv[(size_t)s * 32 + lane];
            if (t & 1) acc_h4(a1, v); else acc_h4(a0, v);
        }
    }
    if (j < k) {
        int idx = j + lane;
        int my = (idx < k) ? g_srcs[start + idx] : 0;
        int m = k - j;
        for (int t = 0; t < m; t++) {
            int s = __shfl_sync(0xFFFFFFFFu, my, t);
            uint2 v = hpv[(size_t)s * 32 + lane];
            if (t & 1) acc_h4(a1, v); else acc_h4(a0, v);
        }
    }

    float sd = g_dis[warp];
    float4 b = ((const float4*)bias)[lane];
    float4 o;
    o.x = fmaf(sd, a0.x + a1.x, b.x);
    o.y = fmaf(sd, a0.y + a1.y, b.y);
    o.z = fmaf(sd, a0.z + a1.z, b.z);
    o.w = fmaf(sd, a0.w + a1.w, b.w);
    ((float4*)out)[(size_t)warp * 32 + lane] = o;
}

// ---------------------------------------------------------------------------
// 7. zero any padding tail of d_out
// ---------------------------------------------------------------------------
__global__ void zero_tail_kernel(float* out, int begin, int end) {
    int i = begin + blockIdx.x * blockDim.x + threadIdx.x;
    if (i < end) out[i] = 0.f;
}

// ---------------------------------------------------------------------------
extern "C" void kernel_launch(void* const* d_in, const int* in_sizes, int n_in,
                              void* d_out, int out_size) {
    const float* x    = (const float*)d_in[0];
    const int*   ei   = (const int*)d_in[1];     // raw words; dtype detected on device
    const float* w    = (const float*)d_in[2];
    const float* bias = (const float*)d_in[3];
    float*       out  = (float*)d_out;

    const int n = in_sizes[0] / D;     // 100000
    const int e = in_sizes[1] / 2;     // 3200000

    // dtype detect + CSR build
    detect_kernel<<<1, 256>>>(ei);
    zero_cnt_kernel<<<(n + 255) / 256, 256>>>(n);
    hist_kernel<<<1024, 256>>>(ei, e, n);
    scan_fused_kernel<<<1, 1024>>>(n);
    fill_kernel<<<1024, 256>>>(ei, e, n);

    // dense transform (needs g_dis), fp16 output
    gemm_kernel<<<(n + TM - 1) / TM, 256>>>(x, w, n);

    // gather aggregation with fused finalize
    {
        long long total_threads = (long long)n * 32;
        int blocks = (int)((total_threads + 255) / 256);
        aggregate_kernel<<<blocks, 256>>>(bias, out, n);
    }

    // padding tail, if any
    if (out_size > n * D) {
        int extra = out_size - n * D;
        zero_tail_kernel<<<(extra + 255) / 256, 256>>>(out, n * D, out_size);
    }
}

// round 6
// speedup vs baseline: 1.6527x; 1.6527x over previous
#include <cuda_runtime.h>
#include <cuda_fp16.h>
#include <cstdint>

#define D 128
#define MAX_N 100000
#define MAX_E 3200000
#define NSCAN 4096            // threads in the scan layer
#define TM 64                 // GEMM row tile

// ---------------------------------------------------------------------------
// Static device scratch
// ---------------------------------------------------------------------------
__device__ int    g_is64;               // 1 if edge_index is int64, 0 if int32
__device__ int    g_cnt [MAX_N];        // in-degree histogram (no self loops)
__device__ int    g_ptr [MAX_N];        // CSR row starts
__device__ int    g_fill[MAX_N];        // fill cursors
__device__ int    g_srcs[MAX_E];        // src ids bucketed by dst
__device__ int    g_tsum[NSCAN];        // per-thread chunk sums
__device__ int    g_tbase[NSCAN];       // per-thread chunk exclusive prefixes
__device__ float  g_dis [MAX_N];        // deg^-1/2 (deg includes self loop)
__device__ __half g_hp  [(size_t)MAX_N * D];   // (x @ W^T) * dis[row], fp16

// ---------------------------------------------------------------------------
// 0. dtype detect: OR odd 32-bit words of the first 2048 "int64 slots".
// ---------------------------------------------------------------------------
__global__ void detect_kernel(const int* __restrict__ p) {
    __shared__ int any;
    if (threadIdx.x == 0) any = 0;
    __syncthreads();
    int v = 0;
    for (int i = threadIdx.x; i < 2048; i += blockDim.x) v |= p[2 * i + 1];
    if (v) atomicOr(&any, 1);
    __syncthreads();
    if (threadIdx.x == 0) g_is64 = (any == 0) ? 1 : 0;
}

// ---------------------------------------------------------------------------
// 1. zero histogram
// ---------------------------------------------------------------------------
__global__ void zero_cnt_kernel(int n) {
    int i = blockIdx.x * blockDim.x + threadIdx.x;
    if (i < n) g_cnt[i] = 0;
}

// ---------------------------------------------------------------------------
// 2. histogram over dst (int4-vectorized int32 fast path)
// ---------------------------------------------------------------------------
__global__ void hist_kernel(const int* __restrict__ p, int e, int n) {
    int gid = blockIdx.x * blockDim.x + threadIdx.x;
    int stride = gridDim.x * blockDim.x;
    if (!g_is64) {
        const int4* d4 = (const int4*)(p + e);
        int e4 = e >> 2;
        for (int i = gid; i < e4; i += stride) {
            int4 v = d4[i];
            if ((unsigned)v.x < (unsigned)n) atomicAdd(&g_cnt[v.x], 1);
            if ((unsigned)v.y < (unsigned)n) atomicAdd(&g_cnt[v.y], 1);
            if ((unsigned)v.z < (unsigned)n) atomicAdd(&g_cnt[v.z], 1);
            if ((unsigned)v.w < (unsigned)n) atomicAdd(&g_cnt[v.w], 1);
        }
        if (gid < (e & 3)) {
            int d = p[(size_t)e + (e & ~3) + gid];
            if ((unsigned)d < (unsigned)n) atomicAdd(&g_cnt[d], 1);
        }
    } else {
        for (int i = gid; i < e; i += stride) {
            int d = p[2 * ((size_t)e + i)];
            if ((unsigned)d < (unsigned)n) atomicAdd(&g_cnt[d], 1);
        }
    }
}

// ---------------------------------------------------------------------------
// 3. scan stage A: per-thread chunk sums (chunk = ceil(n/NSCAN))
// ---------------------------------------------------------------------------
__global__ void scanA_kernel(int n, int chunk) {
    int t = blockIdx.x * blockDim.x + threadIdx.x;
    if (t >= NSCAN) return;
    int b = t * chunk, eend = min(b + chunk, n);
    int s = 0;
    for (int i = b; i < eend; i++) s += g_cnt[i];
    g_tsum[t] = s;
}

// ---------------------------------------------------------------------------
// 4. scan stage B: exclusive scan of NSCAN sums (one block, 1024 threads x 4)
// ---------------------------------------------------------------------------
__global__ __launch_bounds__(1024) void scanB_kernel() {
    __shared__ int sh[1024];
    int t = threadIdx.x;
    int v0 = g_tsum[4 * t + 0], v1 = g_tsum[4 * t + 1];
    int v2 = g_tsum[4 * t + 2], v3 = g_tsum[4 * t + 3];
    int local = v0 + v1 + v2 + v3;
    sh[t] = local;
    __syncthreads();
    for (int off = 1; off < 1024; off <<= 1) {
        int add = (t >= off) ? sh[t - off] : 0;
        __syncthreads();
        sh[t] += add;
        __syncthreads();
    }
    int base = sh[t] - local;   // exclusive
    g_tbase[4 * t + 0] = base;
    g_tbase[4 * t + 1] = base + v0;
    g_tbase[4 * t + 2] = base + v0 + v1;
    g_tbase[4 * t + 3] = base + v0 + v1 + v2;
}

// ---------------------------------------------------------------------------
// 5. scan stage C: write row ptr, fill cursors, and dis = rsqrt(deg+1)
// ---------------------------------------------------------------------------
__global__ void scanC_kernel(int n, int chunk) {
    int t = blockIdx.x * blockDim.x + threadIdx.x;
    if (t >= NSCAN) return;
    int b = t * chunk, eend = min(b + chunk, n);
    int run = g_tbase[t];
    for (int i = b; i < eend; i++) {
        g_ptr[i] = run;
        g_fill[i] = run;
        int c = g_cnt[i];
        g_dis[i] = rsqrtf((float)(c + 1));   // +1 self loop
        run += c;
    }
}

// ---------------------------------------------------------------------------
// 6. fill: bucket src ids by dst (int4-vectorized int32 fast path)
// ---------------------------------------------------------------------------
__device__ __forceinline__ void fill_one(int s, int d, int n) {
    if ((unsigned)d < (unsigned)n) {
        if ((unsigned)s >= (unsigned)n) s = 0;     // defensive clamp
        int pos = atomicAdd(&g_fill[d], 1);
        if (pos < MAX_E) g_srcs[pos] = s;
    }
}

__global__ void fill_kernel(const int* __restrict__ p, int e, int n) {
    int gid = blockIdx.x * blockDim.x + threadIdx.x;
    int stride = gridDim.x * blockDim.x;
    if (!g_is64) {
        const int4* s4 = (const int4*)p;
        const int4* d4 = (const int4*)(p + e);
        int e4 = e >> 2;
        for (int i = gid; i < e4; i += stride) {
            int4 sv = s4[i];
            int4 dv = d4[i];
            fill_one(sv.x, dv.x, n);
            fill_one(sv.y, dv.y, n);
            fill_one(sv.z, dv.z, n);
            fill_one(sv.w, dv.w, n);
        }
        if (gid < (e & 3)) {
            int i = (e & ~3) + gid;
            fill_one(p[i], p[(size_t)e + i], n);
        }
    } else {
        for (int i = gid; i < e; i += stride) {
            int s = p[2 * (size_t)i];
            int d = p[2 * ((size_t)e + i)];
            fill_one(s, d, n);
        }
    }
}

// ---------------------------------------------------------------------------
// 7. GEMM: g_hp[r][c] = half( (sum_k x[r][k] * w[c][k]) * g_dis[r] )
// ---------------------------------------------------------------------------
__global__ __launch_bounds__(256) void gemm_kernel(
    const float* __restrict__ x, const float* __restrict__ w, int n)
{
    __shared__ float xs[TM][64];     // 16 KB
    __shared__ float wt[64][D];      // 32 KB

    const int tx = threadIdx.x & 31;
    const int ty = threadIdx.x >> 5;
    const int row0 = blockIdx.x * TM;

    float acc[8][4];
#pragma unroll
    for (int i = 0; i < 8; i++) { acc[i][0]=0.f; acc[i][1]=0.f; acc[i][2]=0.f; acc[i][3]=0.f; }

    for (int k0 = 0; k0 < D; k0 += 64) {
        for (int i = threadIdx.x; i < TM * 16; i += 256) {
            int r = i >> 4, q = i & 15;
            float4 v = make_float4(0.f, 0.f, 0.f, 0.f);
            if (row0 + r < n)
                v = ((const float4*)(x + (size_t)(row0 + r) * D + k0))[q];
            *(float4*)&xs[r][q * 4] = v;
        }
        for (int i = threadIdx.x; i < D * 16; i += 256) {
            int c = i >> 4, q = i & 15;
            float4 v = ((const float4*)(w + (size_t)c * D + k0))[q];
            wt[q * 4 + 0][c] = v.x;
            wt[q * 4 + 1][c] = v.y;
            wt[q * 4 + 2][c] = v.z;
            wt[q * 4 + 3][c] = v.w;
        }
        __syncthreads();

#pragma unroll
        for (int kk = 0; kk < 64; kk++) {
            float4 wv = *(const float4*)&wt[kk][tx * 4];
#pragma unroll
            for (int i = 0; i < 8; i++) {
                float xv = xs[ty + 8 * i][kk];
                acc[i][0] = fmaf(xv, wv.x, acc[i][0]);
                acc[i][1] = fmaf(xv, wv.y, acc[i][1]);
                acc[i][2] = fmaf(xv, wv.z, acc[i][2]);
                acc[i][3] = fmaf(xv, wv.w, acc[i][3]);
            }
        }
        __syncthreads();
    }

    uint2* hp2 = (uint2*)g_hp;    // 8B = 4 halves per lane
#pragma unroll
    for (int i = 0; i < 8; i++) {
        int r = row0 + ty + 8 * i;
        if (r < n) {
            float s = g_dis[r];
            __half2 h01 = __floats2half2_rn(acc[i][0] * s, acc[i][1] * s);
            __half2 h23 = __floats2half2_rn(acc[i][2] * s, acc[i][3] * s);
            uint2 o;
            o.x = *reinterpret_cast<unsigned*>(&h01);
            o.y = *reinterpret_cast<unsigned*>(&h23);
            hp2[(size_t)r * 32 + tx] = o;
        }
    }
}

// ---------------------------------------------------------------------------
// 8. gather-aggregate: one warp per node, fp16 gather, fp32 accumulate.
// ---------------------------------------------------------------------------
__device__ __forceinline__ void acc_h4(float4& a, uint2 v) {
    __half2 h0 = *reinterpret_cast<__half2*>(&v.x);
    __half2 h1 = *reinterpret_cast<__half2*>(&v.y);
    float2 f0 = __half22float2(h0);
    float2 f1 = __half22float2(h1);
    a.x += f0.x; a.y += f0.y; a.z += f1.x; a.w += f1.y;
}

__global__ __launch_bounds__(256) void aggregate_kernel(
    const float* __restrict__ bias, float* __restrict__ out, int n)
{
    int warp = (blockIdx.x * blockDim.x + threadIdx.x) >> 5;
    int lane = threadIdx.x & 31;
    if (warp >= n) return;

    const uint2* hpv = (const uint2*)g_hp;
    int start = g_ptr[warp];
    int k = g_cnt[warp];

    float4 a0 = make_float4(0.f, 0.f, 0.f, 0.f);
    float4 a1 = make_float4(0.f, 0.f, 0.f, 0.f);
    acc_h4(a0, hpv[(size_t)warp * 32 + lane]);      // self-loop term

    int full = k & ~31;
    int j = 0;
    for (; j < full; j += 32) {
        int my = g_srcs[start + j + lane];
#pragma unroll
        for (int t = 0; t < 32; t++) {
            int s = __shfl_sync(0xFFFFFFFFu, my, t);
            uint2 v = hpv[(size_t)s * 32 + lane];
            if (t & 1) acc_h4(a1, v); else acc_h4(a0, v);
        }
    }
    if (j < k) {
        int idx = j + lane;
        int my = (idx < k) ? g_srcs[start + idx] : 0;
        int m = k - j;
        for (int t = 0; t < m; t++) {
            int s = __shfl_sync(0xFFFFFFFFu, my, t);
            uint2 v = hpv[(size_t)s * 32 + lane];
            if (t & 1) acc_h4(a1, v); else acc_h4(a0, v);
        }
    }

    float sd = g_dis[warp];
    float4 b = ((const float4*)bias)[lane];
    float4 o;
    o.x = fmaf(sd, a0.x + a1.x, b.x);
    o.y = fmaf(sd, a0.y + a1.y, b.y);
    o.z = fmaf(sd, a0.z + a1.z, b.z);
    o.w = fmaf(sd, a0.w + a1.w, b.w);
    ((float4*)out)[(size_t)warp * 32 + lane] = o;
}

// ---------------------------------------------------------------------------
// 9. zero any padding tail of d_out
// ---------------------------------------------------------------------------
__global__ void zero_tail_kernel(float* out, int begin, int end) {
    int i = begin + blockIdx.x * blockDim.x + threadIdx.x;
    if (i < end) out[i] = 0.f;
}

// ---------------------------------------------------------------------------
extern "C" void kernel_launch(void* const* d_in, const int* in_sizes, int n_in,
                              void* d_out, int out_size) {
    const float* x    = (const float*)d_in[0];
    const int*   ei   = (const int*)d_in[1];     // raw words; dtype detected on device
    const float* w    = (const float*)d_in[2];
    const float* bias = (const float*)d_in[3];
    float*       out  = (float*)d_out;

    const int n = in_sizes[0] / D;     // 100000
    const int e = in_sizes[1] / 2;     // 3200000

    const int chunk = (n + NSCAN - 1) / NSCAN;

    // dtype detect + CSR build (multi-block scan: the round-5 fused single-block
    // scan cost 217us on one SM; this chain costs ~15us)
    detect_kernel<<<1, 256>>>(ei);
    zero_cnt_kernel<<<(n + 255) / 256, 256>>>(n);
    hist_kernel<<<2048, 256>>>(ei, e, n);
    scanA_kernel<<<NSCAN / 256, 256>>>(n, chunk);
    scanB_kernel<<<1, 1024>>>();
    scanC_kernel<<<NSCAN / 256, 256>>>(n, chunk);
    fill_kernel<<<2048, 256>>>(ei, e, n);

    // dense transform (needs g_dis), fp16 output
    gemm_kernel<<<(n + TM - 1) / TM, 256>>>(x, w, n);

    // gather aggregation with fused finalize
    {
        long long total_threads = (long long)n * 32;
        int blocks = (int)((total_threads + 255) / 256);
        aggregate_kernel<<<blocks, 256>>>(bias, out, n);
    }

    // padding tail, if any
    if (out_size > n * D) {
        int extra = out_size - n * D;
        zero_tail_kernel<<<(extra + 255) / 256, 256>>>(out, n * D, out_size);
    }
}

// round 9
// speedup vs baseline: 2.2549x; 1.3643x over previous
#include <cuda_runtime.h>
#include <cuda_fp16.h>
#include <cstdint>

#define D 128
#define MAX_N 100000
#define MAX_E 3200000
#define NSCAN 4096
#define BM 32                 // GEMM row tile (mma version)

// ---------------------------------------------------------------------------
// Static device scratch
// ---------------------------------------------------------------------------
__device__ int    g_is64;
__device__ int    g_cnt [MAX_N];
__device__ int    g_ptr [MAX_N];
__device__ int    g_fill[MAX_N];
__device__ int    g_srcs[MAX_E];
__device__ int    g_tsum[NSCAN];
__device__ int    g_tbase[NSCAN];
__device__ float  g_dis [MAX_N];
__device__ __half g_wh  [D * D];               // W in fp16 (row c, 128 k)
__device__ __half g_hp  [(size_t)MAX_N * D];   // (x @ W^T) * dis[row], fp16

// ---------------------------------------------------------------------------
// 0. dtype detect
// ---------------------------------------------------------------------------
__global__ void detect_kernel(const int* __restrict__ p) {
    __shared__ int any;
    if (threadIdx.x == 0) any = 0;
    __syncthreads();
    int v = 0;
    for (int i = threadIdx.x; i < 2048; i += blockDim.x) v |= p[2 * i + 1];
    if (v) atomicOr(&any, 1);
    __syncthreads();
    if (threadIdx.x == 0) g_is64 = (any == 0) ? 1 : 0;
}

// ---------------------------------------------------------------------------
// 1. zero histogram
// ---------------------------------------------------------------------------
__global__ void zero_cnt_kernel(int n) {
    int i = blockIdx.x * blockDim.x + threadIdx.x;
    if (i < n) g_cnt[i] = 0;
}

// ---------------------------------------------------------------------------
// 2. histogram over dst (int4-vectorized int32 fast path)
// ---------------------------------------------------------------------------
__global__ void hist_kernel(const int* __restrict__ p, int e, int n) {
    int gid = blockIdx.x * blockDim.x + threadIdx.x;
    int stride = gridDim.x * blockDim.x;
    if (!g_is64) {
        const int4* d4 = (const int4*)(p + e);
        int e4 = e >> 2;
        for (int i = gid; i < e4; i += stride) {
            int4 v = d4[i];
            if ((unsigned)v.x < (unsigned)n) atomicAdd(&g_cnt[v.x], 1);
            if ((unsigned)v.y < (unsigned)n) atomicAdd(&g_cnt[v.y], 1);
            if ((unsigned)v.z < (unsigned)n) atomicAdd(&g_cnt[v.z], 1);
            if ((unsigned)v.w < (unsigned)n) atomicAdd(&g_cnt[v.w], 1);
        }
        if (gid < (e & 3)) {
            int d = p[(size_t)e + (e & ~3) + gid];
            if ((unsigned)d < (unsigned)n) atomicAdd(&g_cnt[d], 1);
        }
    } else {
        for (int i = gid; i < e; i += stride) {
            int d = p[2 * ((size_t)e + i)];
            if ((unsigned)d < (unsigned)n) atomicAdd(&g_cnt[d], 1);
        }
    }
}

// ---------------------------------------------------------------------------
// 3-5. multi-block scan
// ---------------------------------------------------------------------------
__global__ void scanA_kernel(int n, int chunk) {
    int t = blockIdx.x * blockDim.x + threadIdx.x;
    if (t >= NSCAN) return;
    int b = t * chunk, eend = min(b + chunk, n);
    int s = 0;
    for (int i = b; i < eend; i++) s += g_cnt[i];
    g_tsum[t] = s;
}

__global__ __launch_bounds__(1024) void scanB_kernel() {
    __shared__ int sh[1024];
    int t = threadIdx.x;
    int v0 = g_tsum[4 * t + 0], v1 = g_tsum[4 * t + 1];
    int v2 = g_tsum[4 * t + 2], v3 = g_tsum[4 * t + 3];
    int local = v0 + v1 + v2 + v3;
    sh[t] = local;
    __syncthreads();
    for (int off = 1; off < 1024; off <<= 1) {
        int add = (t >= off) ? sh[t - off] : 0;
        __syncthreads();
        sh[t] += add;
        __syncthreads();
    }
    int base = sh[t] - local;
    g_tbase[4 * t + 0] = base;
    g_tbase[4 * t + 1] = base + v0;
    g_tbase[4 * t + 2] = base + v0 + v1;
    g_tbase[4 * t + 3] = base + v0 + v1 + v2;
}

__global__ void scanC_kernel(int n, int chunk) {
    int t = blockIdx.x * blockDim.x + threadIdx.x;
    if (t >= NSCAN) return;
    int b = t * chunk, eend = min(b + chunk, n);
    int run = g_tbase[t];
    for (int i = b; i < eend; i++) {
        g_ptr[i] = run;
        g_fill[i] = run;
        int c = g_cnt[i];
        g_dis[i] = rsqrtf((float)(c + 1));
        run += c;
    }
}

// ---------------------------------------------------------------------------
// 6. fill: bucket src ids by dst
// ---------------------------------------------------------------------------
__device__ __forceinline__ void fill_one(int s, int d, int n) {
    if ((unsigned)d < (unsigned)n) {
        if ((unsigned)s >= (unsigned)n) s = 0;
        int pos = atomicAdd(&g_fill[d], 1);
        if (pos < MAX_E) g_srcs[pos] = s;
    }
}

__global__ void fill_kernel(const int* __restrict__ p, int e, int n) {
    int gid = blockIdx.x * blockDim.x + threadIdx.x;
    int stride = gridDim.x * blockDim.x;
    if (!g_is64) {
        const int4* s4 = (const int4*)p;
        const int4* d4 = (const int4*)(p + e);
        int e4 = e >> 2;
        for (int i = gid; i < e4; i += stride) {
            int4 sv = s4[i];
            int4 dv = d4[i];
            fill_one(sv.x, dv.x, n);
            fill_one(sv.y, dv.y, n);
            fill_one(sv.z, dv.z, n);
            fill_one(sv.w, dv.w, n);
        }
        if (gid < (e & 3)) {
            int i = (e & ~3) + gid;
            fill_one(p[i], p[(size_t)e + i], n);
        }
    } else {
        for (int i = gid; i < e; i += stride) {
            int s = p[2 * (size_t)i];
            int d = p[2 * ((size_t)e + i)];
            fill_one(s, d, n);
        }
    }
}

// ---------------------------------------------------------------------------
// 7a. convert W to fp16 once
// ---------------------------------------------------------------------------
__global__ void convert_w_kernel(const float* __restrict__ w) {
    int i = blockIdx.x * blockDim.x + threadIdx.x;
    if (i < D * D / 2) {
        float2 v = ((const float2*)w)[i];
        ((__half2*)g_wh)[i] = __floats2half2_rn(v.x, v.y);
    }
}

// ---------------------------------------------------------------------------
// 7b. tensor-core GEMM: g_hp[r][c] = half( (x[r]·w[c]) * dis[r] )
//     Block: 256 thr (8 warps), BM=32 rows x 128 cols.
//     Warp w: rows 16*(w&1).., cols 32*(w>>1)..  (4 n-tiles of 8)
// ---------------------------------------------------------------------------
__global__ __launch_bounds__(256) void gemm_mma_kernel(
    const float* __restrict__ x, int n)
{
    __shared__ __half sx[BM][136];    // padded stride: conflict-free ldmatrix
    __shared__ __half sw[D][136];

    const int t = threadIdx.x;
    const int row0 = blockIdx.x * BM;

    // stage x tile (fp32 -> fp16)
    {
        int r = t >> 3, cseg = (t & 7) * 16;
        int gr = row0 + r;
        const float4* xp = (const float4*)(x + (size_t)gr * D + cseg);
#pragma unroll
        for (int q = 0; q < 4; q++) {
            float4 v = (gr < n) ? xp[q] : make_float4(0.f, 0.f, 0.f, 0.f);
            *(__half2*)&sx[r][cseg + 4 * q]     = __floats2half2_rn(v.x, v.y);
            *(__half2*)&sx[r][cseg + 4 * q + 2] = __floats2half2_rn(v.z, v.w);
        }
    }
    // stage W tile (already fp16)
    {
        int r = t >> 1, cseg = (t & 1) * 64;
        const uint4* wp = (const uint4*)(g_wh + r * D + cseg);
#pragma unroll
        for (int q = 0; q < 8; q++)
            *(uint4*)&sw[r][cseg + 8 * q] = wp[q];
    }
    __syncthreads();

    const int wid = t >> 5, lane = t & 31;
    const int mrow0 = (wid & 1) * 16;
    const int ncol0 = (wid >> 1) * 32;

    float acc[4][4];
#pragma unroll
    for (int i = 0; i < 4; i++) { acc[i][0]=0.f; acc[i][1]=0.f; acc[i][2]=0.f; acc[i][3]=0.f; }

    const int arow = mrow0 + (lane & 15);
    const int acol = (lane >> 4) * 8;
    const int brow = (lane & 7);
    const int bcol = ((lane >> 3) & 1) * 8;

#pragma unroll
    for (int k0 = 0; k0 < D; k0 += 16) {
        unsigned aaddr = (unsigned)__cvta_generic_to_shared(&sx[arow][k0 + acol]);
        uint32_t a0, a1, a2, a3;
        asm volatile("ldmatrix.sync.aligned.m8n8.x4.shared.b16 {%0,%1,%2,%3}, [%4];"
                     : "=r"(a0), "=r"(a1), "=r"(a2), "=r"(a3) : "r"(aaddr));
#pragma unroll
        for (int nt = 0; nt < 4; nt++) {
            unsigned baddr = (unsigned)__cvta_generic_to_shared(
                &sw[ncol0 + nt * 8 + brow][k0 + bcol]);
            uint32_t b0, b1;
            asm volatile("ldmatrix.sync.aligned.m8n8.x2.shared.b16 {%0,%1}, [%2];"
                         : "=r"(b0), "=r"(b1) : "r"(baddr));
            asm volatile("mma.sync.aligned.m16n8k16.row.col.f32.f16.f16.f32 "
                         "{%0,%1,%2,%3}, {%4,%5,%6,%7}, {%8,%9}, {%0,%1,%2,%3};"
                         : "+f"(acc[nt][0]), "+f"(acc[nt][1]),
                           "+f"(acc[nt][2]), "+f"(acc[nt][3])
                         : "r"(a0), "r"(a1), "r"(a2), "r"(a3), "r"(b0), "r"(b1));
        }
    }

    // epilogue: scale by dis[row], convert to fp16
    const int g = lane >> 2, tid4 = lane & 3;
    const int r0 = row0 + mrow0 + g;
    const int r1 = r0 + 8;
    float s0 = (r0 < n) ? g_dis[r0] : 0.f;
    float s1 = (r1 < n) ? g_dis[r1] : 0.f;
    __half2* hp2 = (__half2*)g_hp;
#pragma unroll
    for (int nt = 0; nt < 4; nt++) {
        int c = ncol0 + nt * 8 + 2 * tid4;
        if (r0 < n) hp2[(size_t)r0 * 64 + (c >> 1)] = __floats2half2_rn(acc[nt][0] * s0, acc[nt][1] * s0);
        if (r1 < n) hp2[(size_t)r1 * 64 + (c >> 1)] = __floats2half2_rn(acc[nt][2] * s1, acc[nt][3] * s1);
    }
}

// ---------------------------------------------------------------------------
// 8. gather-aggregate: one warp per node, TWO edges per iteration.
//    Lane group 0 (0-15) handles even edge, group 1 (16-31) odd edge.
//    Each lane loads 16B (8 halves). Combine via shfl_down(16) at the end.
// ---------------------------------------------------------------------------
__device__ __forceinline__ void add8(float* a, uint4 v) {
    float2 f;
    f = __half22float2(*(__half2*)&v.x); a[0] += f.x; a[1] += f.y;
    f = __half22float2(*(__half2*)&v.y); a[2] += f.x; a[3] += f.y;
    f = __half22float2(*(__half2*)&v.z); a[4] += f.x; a[5] += f.y;
    f = __half22float2(*(__half2*)&v.w); a[6] += f.x; a[7] += f.y;
}

__global__ __launch_bounds__(256) void aggregate_kernel(
    const float* __restrict__ bias, float* __restrict__ out, int n)
{
    int node = (blockIdx.x * blockDim.x + threadIdx.x) >> 5;
    int lane = threadIdx.x & 31;
    if (node >= n) return;
    const int half_id = lane >> 4;
    const int sub = lane & 15;

    const uint4* hp16 = (const uint4*)g_hp;   // 16 uint4 per 128-half row
    int start = g_ptr[node];
    int k = g_cnt[node];

    float acc[8] = {0.f, 0.f, 0.f, 0.f, 0.f, 0.f, 0.f, 0.f};
    if (half_id == 0) add8(acc, hp16[(size_t)node * 16 + sub]);   // self loop

    int j = 0;
    int full = k & ~31;
    for (; j < full; j += 32) {
        int my = g_srcs[start + j + lane];
#pragma unroll
        for (int t2 = 0; t2 < 16; t2++) {
            int s = __shfl_sync(0xFFFFFFFFu, my, 2 * t2 + half_id);
            add8(acc, hp16[(size_t)s * 16 + sub]);
        }
    }
    int m = k - j;
    if (m > 0) {
        int idx = j + lane;
        int my = (idx < k) ? g_srcs[start + idx] : 0;
        int pairs = m >> 1;
        for (int t2 = 0; t2 < pairs; t2++) {
            int s = __shfl_sync(0xFFFFFFFFu, my, 2 * t2 + half_id);
            add8(acc, hp16[(size_t)s * 16 + sub]);
        }
        if (m & 1) {
            int s = __shfl_sync(0xFFFFFFFFu, my, m - 1);
            if (half_id == 0) add8(acc, hp16[(size_t)s * 16 + sub]);
        }
    }

#pragma unroll
    for (int i = 0; i < 8; i++)
        acc[i] += __shfl_down_sync(0xFFFFFFFFu, acc[i], 16);

    if (half_id == 0) {
        float sd = g_dis[node];
        const float4* b4 = (const float4*)bias;
        float4 ba = b4[sub * 2], bb = b4[sub * 2 + 1];
        float4 o0, o1;
        o0.x = fmaf(sd, acc[0], ba.x);
        o0.y = fmaf(sd, acc[1], ba.y);
        o0.z = fmaf(sd, acc[2], ba.z);
        o0.w = fmaf(sd, acc[3], ba.w);
        o1.x = fmaf(sd, acc[4], bb.x);
        o1.y = fmaf(sd, acc[5], bb.y);
        o1.z = fmaf(sd, acc[6], bb.z);
        o1.w = fmaf(sd, acc[7], bb.w);
        float4* op = (float4*)out + (size_t)node * 32 + sub * 2;
        op[0] = o0;
        op[1] = o1;
    }
}

// ---------------------------------------------------------------------------
// 9. zero any padding tail of d_out
// ---------------------------------------------------------------------------
__global__ void zero_tail_kernel(float* out, int begin, int end) {
    int i = begin + blockIdx.x * blockDim.x + threadIdx.x;
    if (i < end) out[i] = 0.f;
}

// ---------------------------------------------------------------------------
extern "C" void kernel_launch(void* const* d_in, const int* in_sizes, int n_in,
                              void* d_out, int out_size) {
    const float* x    = (const float*)d_in[0];
    const int*   ei   = (const int*)d_in[1];
    const float* w    = (const float*)d_in[2];
    const float* bias = (const float*)d_in[3];
    float*       out  = (float*)d_out;

    const int n = in_sizes[0] / D;     // 100000
    const int e = in_sizes[1] / 2;     // 3200000

    const int chunk = (n + NSCAN - 1) / NSCAN;

    // dtype detect + CSR build
    detect_kernel<<<1, 256>>>(ei);
    zero_cnt_kernel<<<(n + 255) / 256, 256>>>(n);
    hist_kernel<<<2048, 256>>>(ei, e, n);
    convert_w_kernel<<<(D * D / 2 + 255) / 256, 256>>>(w);   // independent
    scanA_kernel<<<NSCAN / 256, 256>>>(n, chunk);
    scanB_kernel<<<1, 1024>>>();
    scanC_kernel<<<NSCAN / 256, 256>>>(n, chunk);
    fill_kernel<<<2048, 256>>>(ei, e, n);

    // tensor-core dense transform (needs g_dis + g_wh)
    gemm_mma_kernel<<<(n + BM - 1) / BM, 256>>>(x, n);

    // gather aggregation with fused finalize
    {
        long long total_threads = (long long)n * 32;
        int blocks = (int)((total_threads + 255) / 256);
        aggregate_kernel<<<blocks, 256>>>(bias, out, n);
    }

    if (out_size > n * D) {
        int extra = out_size - n * D;
        zero_tail_kernel<<<(extra + 255) / 256, 256>>>(out, n * D, out_size);
    }
}

// round 12
// speedup vs baseline: 2.6369x; 1.1694x over previous
#include <cuda_runtime.h>
#include <cuda_fp16.h>
#include <cstdint>

#define D 128
#define MAX_N 100000
#define MAX_E 3200000
#define BINSZ 96              // fixed per-node bucket (deg ~ Poisson(32); 96 = +11 sigma)
#define MAX_SPILL 2048
#define BM 32                 // GEMM row tile

// ---------------------------------------------------------------------------
// Static device scratch
// ---------------------------------------------------------------------------
__device__ int    g_is64;
__device__ int    g_cnt [MAX_N];                   // atomic degree counters
__device__ int    g_bins[(size_t)MAX_N * BINSZ];   // src ids, fixed stride
__device__ int    g_spillcnt;
__device__ int2   g_spill[MAX_SPILL];              // (src, dst) overflow edges
__device__ float  g_dis [MAX_N];                   // (deg+1)^-1/2
__device__ __half g_wh  [D * D];                   // W fp16
__device__ __half g_hp  [(size_t)MAX_N * D];       // (x @ W^T) * dis[row], fp16

// ---------------------------------------------------------------------------
// 1. prep: zero counters + detect edge dtype + convert W to fp16 (one kernel)
// ---------------------------------------------------------------------------
__global__ void prep_kernel(const float* __restrict__ w, const int* __restrict__ p, int n) {
    int gid = blockIdx.x * blockDim.x + threadIdx.x;
    if (gid < n) g_cnt[gid] = 0;
    if (gid == 0) g_spillcnt = 0;
    if (gid < D * D / 2) {
        float2 v = ((const float2*)w)[gid];
        ((__half2*)g_wh)[gid] = __floats2half2_rn(v.x, v.y);
    }
    if (blockIdx.x == 0) {               // dtype detect: odd words of first 2048 i64 slots
        __shared__ int any;
        if (threadIdx.x == 0) any = 0;
        __syncthreads();
        int v = 0;
        for (int i = threadIdx.x; i < 2048; i += blockDim.x) v |= p[2 * i + 1];
        if (v) atomicOr(&any, 1);
        __syncthreads();
        if (threadIdx.x == 0) g_is64 = (any == 0) ? 1 : 0;
    }
}

// ---------------------------------------------------------------------------
// 2. fill: single edge pass builds binned adjacency + degree counts
// ---------------------------------------------------------------------------
__device__ __forceinline__ void fill_one(int s, int d, int n) {
    if ((unsigned)d < (unsigned)n) {
        if ((unsigned)s >= (unsigned)n) s = 0;           // defensive clamp
        int pos = atomicAdd(&g_cnt[d], 1);
        if (pos < BINSZ) {
            g_bins[(size_t)d * BINSZ + pos] = s;
        } else {
            int sp = atomicAdd(&g_spillcnt, 1);
            if (sp < MAX_SPILL) g_spill[sp] = make_int2(s, d);
        }
    }
}

__global__ void fill_kernel(const int* __restrict__ p, int e, int n) {
    int gid = blockIdx.x * blockDim.x + threadIdx.x;
    int stride = gridDim.x * blockDim.x;
    if (!g_is64) {
        const int4* s4 = (const int4*)p;
        const int4* d4 = (const int4*)(p + e);
        int e4 = e >> 2;
        for (int i = gid; i < e4; i += stride) {
            int4 sv = s4[i];
            int4 dv = d4[i];
            fill_one(sv.x, dv.x, n);
            fill_one(sv.y, dv.y, n);
            fill_one(sv.z, dv.z, n);
            fill_one(sv.w, dv.w, n);
        }
        if (gid < (e & 3)) {
            int i = (e & ~3) + gid;
            fill_one(p[i], p[(size_t)e + i], n);
        }
    } else {
        for (int i = gid; i < e; i += stride) {
            int s = p[2 * (size_t)i];
            int d = p[2 * ((size_t)e + i)];
            fill_one(s, d, n);
        }
    }
}

// ---------------------------------------------------------------------------
// 3. dis = rsqrt(deg + 1)
// ---------------------------------------------------------------------------
__global__ void dis_kernel(int n) {
    int i = blockIdx.x * blockDim.x + threadIdx.x;
    if (i < n) g_dis[i] = rsqrtf((float)(g_cnt[i] + 1));
}

// ---------------------------------------------------------------------------
// 4. tensor-core GEMM: g_hp[r][c] = half( (x[r]·w[c]) * dis[r] )
//    256 thr (8 warps), BM=32 rows x 128 cols per block.
// ---------------------------------------------------------------------------
__global__ __launch_bounds__(256) void gemm_mma_kernel(
    const float* __restrict__ x, int n)
{
    __shared__ __half sx[BM][136];
    __shared__ __half sw[D][136];

    const int t = threadIdx.x;
    const int row0 = blockIdx.x * BM;

    {   // stage x tile (fp32 -> fp16)
        int r = t >> 3, cseg = (t & 7) * 16;
        int gr = row0 + r;
        const float4* xp = (const float4*)(x + (size_t)gr * D + cseg);
#pragma unroll
        for (int q = 0; q < 4; q++) {
            float4 v = (gr < n) ? xp[q] : make_float4(0.f, 0.f, 0.f, 0.f);
            *(__half2*)&sx[r][cseg + 4 * q]     = __floats2half2_rn(v.x, v.y);
            *(__half2*)&sx[r][cseg + 4 * q + 2] = __floats2half2_rn(v.z, v.w);
        }
    }
    {   // stage W tile
        int r = t >> 1, cseg = (t & 1) * 64;
        const uint4* wp = (const uint4*)(g_wh + r * D + cseg);
#pragma unroll
        for (int q = 0; q < 8; q++)
            *(uint4*)&sw[r][cseg + 8 * q] = wp[q];
    }
    __syncthreads();

    const int wid = t >> 5, lane = t & 31;
    const int mrow0 = (wid & 1) * 16;
    const int ncol0 = (wid >> 1) * 32;

    float acc[4][4];
#pragma unroll
    for (int i = 0; i < 4; i++) { acc[i][0]=0.f; acc[i][1]=0.f; acc[i][2]=0.f; acc[i][3]=0.f; }

    const int arow = mrow0 + (lane & 15);
    const int acol = (lane >> 4) * 8;
    const int brow = (lane & 7);
    const int bcol = ((lane >> 3) & 1) * 8;

#pragma unroll
    for (int k0 = 0; k0 < D; k0 += 16) {
        unsigned aaddr = (unsigned)__cvta_generic_to_shared(&sx[arow][k0 + acol]);
        uint32_t a0, a1, a2, a3;
        asm volatile("ldmatrix.sync.aligned.m8n8.x4.shared.b16 {%0,%1,%2,%3}, [%4];"
                     : "=r"(a0), "=r"(a1), "=r"(a2), "=r"(a3) : "r"(aaddr));
#pragma unroll
        for (int nt = 0; nt < 4; nt++) {
            unsigned baddr = (unsigned)__cvta_generic_to_shared(
                &sw[ncol0 + nt * 8 + brow][k0 + bcol]);
            uint32_t b0, b1;
            asm volatile("ldmatrix.sync.aligned.m8n8.x2.shared.b16 {%0,%1}, [%2];"
                         : "=r"(b0), "=r"(b1) : "r"(baddr));
            asm volatile("mma.sync.aligned.m16n8k16.row.col.f32.f16.f16.f32 "
                         "{%0,%1,%2,%3}, {%4,%5,%6,%7}, {%8,%9}, {%0,%1,%2,%3};"
                         : "+f"(acc[nt][0]), "+f"(acc[nt][1]),
                           "+f"(acc[nt][2]), "+f"(acc[nt][3])
                         : "r"(a0), "r"(a1), "r"(a2), "r"(a3), "r"(b0), "r"(b1));
        }
    }

    const int g = lane >> 2, tid4 = lane & 3;
    const int r0 = row0 + mrow0 + g;
    const int r1 = r0 + 8;
    float s0 = (r0 < n) ? g_dis[r0] : 0.f;
    float s1 = (r1 < n) ? g_dis[r1] : 0.f;
    __half2* hp2 = (__half2*)g_hp;
#pragma unroll
    for (int nt = 0; nt < 4; nt++) {
        int c = ncol0 + nt * 8 + 2 * tid4;
        if (r0 < n) hp2[(size_t)r0 * 64 + (c >> 1)] = __floats2half2_rn(acc[nt][0] * s0, acc[nt][1] * s0);
        if (r1 < n) hp2[(size_t)r1 * 64 + (c >> 1)] = __floats2half2_rn(acc[nt][2] * s1, acc[nt][3] * s1);
    }
}

// ---------------------------------------------------------------------------
// 5. gather-aggregate: one warp per node, two edges per iteration.
// ---------------------------------------------------------------------------
__device__ __forceinline__ void add8(float* a, uint4 v) {
    float2 f;
    f = __half22float2(*(__half2*)&v.x); a[0] += f.x; a[1] += f.y;
    f = __half22float2(*(__half2*)&v.y); a[2] += f.x; a[3] += f.y;
    f = __half22float2(*(__half2*)&v.z); a[4] += f.x; a[5] += f.y;
    f = __half22float2(*(__half2*)&v.w); a[6] += f.x; a[7] += f.y;
}

__global__ __launch_bounds__(256) void aggregate_kernel(
    const float* __restrict__ bias, float* __restrict__ out, int n)
{
    int node = (blockIdx.x * blockDim.x + threadIdx.x) >> 5;
    int lane = threadIdx.x & 31;
    if (node >= n) return;
    const int half_id = lane >> 4;
    const int sub = lane & 15;

    const uint4* hp16 = (const uint4*)g_hp;
    const int start = node * BINSZ;
    int k = g_cnt[node];
    if (k > BINSZ) k = BINSZ;            // spilled edges handled separately

    float acc[8] = {0.f, 0.f, 0.f, 0.f, 0.f, 0.f, 0.f, 0.f};
    if (half_id == 0) add8(acc, hp16[(size_t)node * 16 + sub]);   // self loop

    int j = 0;
    int full = k & ~31;
    for (; j < full; j += 32) {
        int my = g_bins[start + j + lane];
#pragma unroll
        for (int t2 = 0; t2 < 16; t2++) {
            int s = __shfl_sync(0xFFFFFFFFu, my, 2 * t2 + half_id);
            add8(acc, hp16[(size_t)s * 16 + sub]);
        }
    }
    int m = k - j;
    if (m > 0) {
        int idx = j + lane;
        int my = (idx < k) ? g_bins[start + idx] : 0;
        int pairs = m >> 1;
        for (int t2 = 0; t2 < pairs; t2++) {
            int s = __shfl_sync(0xFFFFFFFFu, my, 2 * t2 + half_id);
            add8(acc, hp16[(size_t)s * 16 + sub]);
        }
        if (m & 1) {
            int s = __shfl_sync(0xFFFFFFFFu, my, m - 1);
            if (half_id == 0) add8(acc, hp16[(size_t)s * 16 + sub]);
        }
    }

#pragma unroll
    for (int i = 0; i < 8; i++)
        acc[i] += __shfl_down_sync(0xFFFFFFFFu, acc[i], 16);

    if (half_id == 0) {
        float sd = g_dis[node];
        const float4* b4 = (const float4*)bias;
        float4 ba = b4[sub * 2], bb = b4[sub * 2 + 1];
        float4 o0, o1;
        o0.x = fmaf(sd, acc[0], ba.x);
        o0.y = fmaf(sd, acc[1], ba.y);
        o0.z = fmaf(sd, acc[2], ba.z);
        o0.w = fmaf(sd, acc[3], ba.w);
        o1.x = fmaf(sd, acc[4], bb.x);
        o1.y = fmaf(sd, acc[5], bb.y);
        o1.z = fmaf(sd, acc[6], bb.z);
        o1.w = fmaf(sd, acc[7], bb.w);
        float4* op = (float4*)out + (size_t)node * 32 + sub * 2;
        op[0] = o0;
        op[1] = o1;
    }
}

// ---------------------------------------------------------------------------
// 6. spill fixup (normally zero work): out[d] += dis[d] * hp[s]
// ---------------------------------------------------------------------------
__global__ void spill_kernel(float* __restrict__ out) {
    int nsp = g_spillcnt;
    if (nsp > MAX_SPILL) nsp = MAX_SPILL;
    int warp = (blockIdx.x * blockDim.x + threadIdx.x) >> 5;
    int lane = threadIdx.x & 31;
    int wstride = (gridDim.x * blockDim.x) >> 5;
    for (int i = warp; i < nsp; i += wstride) {
        int2 ed = g_spill[i];
        float sd = g_dis[ed.y];
        uint2 v = ((const uint2*)g_hp)[(size_t)ed.x * 32 + lane];   // 4 halves
        float2 f0 = __half22float2(*(__half2*)&v.x);
        float2 f1 = __half22float2(*(__half2*)&v.y);
        float* o = out + (size_t)ed.y * D + lane * 4;
        atomicAdd(o + 0, sd * f0.x);
        atomicAdd(o + 1, sd * f0.y);
        atomicAdd(o + 2, sd * f1.x);
        atomicAdd(o + 3, sd * f1.y);
    }
}

// ---------------------------------------------------------------------------
// 7. zero any padding tail of d_out
// ---------------------------------------------------------------------------
__global__ void zero_tail_kernel(float* out, int begin, int end) {
    int i = begin + blockIdx.x * blockDim.x + threadIdx.x;
    if (i < end) out[i] = 0.f;
}

// ---------------------------------------------------------------------------
extern "C" void kernel_launch(void* const* d_in, const int* in_sizes, int n_in,
                              void* d_out, int out_size) {
    const float* x    = (const float*)d_in[0];
    const int*   ei   = (const int*)d_in[1];
    const float* w    = (const float*)d_in[2];
    const float* bias = (const float*)d_in[3];
    float*       out  = (float*)d_out;

    const int n = in_sizes[0] / D;     // 100000
    const int e = in_sizes[1] / 2;     // 3200000

    // 1. zero counters + dtype detect + W conversion (fused)
    prep_kernel<<<(n + 255) / 256, 256>>>(w, ei, n);

    // 2. single edge pass: binned adjacency + degrees
    fill_kernel<<<2048, 256>>>(ei, e, n);

    // 3. dis = rsqrt(deg + 1)
    dis_kernel<<<(n + 255) / 256, 256>>>(n);

    // 4. tensor-core dense transform
    gemm_mma_kernel<<<(n + BM - 1) / BM, 256>>>(x, n);

    // 5. gather aggregation with fused finalize
    {
        long long total_threads = (long long)n * 32;
        int blocks = (int)((total_threads + 255) / 256);
        aggregate_kernel<<<blocks, 256>>>(bias, out, n);
    }

    // 6. spill fixup (no-op unless a node exceeded BINSZ)
    spill_kernel<<<64, 256>>>(out);

    // 7. padding tail, if any
    if (out_size > n * D) {
        int extra = out_size - n * D;
        zero_tail_kernel<<<(extra + 255) / 256, 256>>>(out, n * D, out_size);
    }
}

// round 13
// speedup vs baseline: 3.0068x; 1.1403x over previous
#include <cuda_runtime.h>
#include <cuda_fp16.h>
#include <cstdint>

#define D 128
#define MAX_N 100000
#define MAX_E 3200000
#define BINSZ 96              // fixed per-node bucket (deg ~ Poisson(32); 96 = +11 sigma)
#define MAX_SPILL 2048
#define BM 32                 // rows per group
#define GROUPS 8              // row-groups per block (256 rows/block)

// ---------------------------------------------------------------------------
// Static device scratch
// ---------------------------------------------------------------------------
__device__ int    g_is64;
__device__ int    g_cnt [MAX_N];                   // atomic degree counters
__device__ int    g_bins[(size_t)MAX_N * BINSZ];   // src ids, fixed stride
__device__ int    g_spillcnt;
__device__ int2   g_spill[MAX_SPILL];              // (src, dst) overflow edges
__device__ float  g_dis [MAX_N];                   // (deg+1)^-1/2
__device__ __half g_wh  [D * D];                   // W fp16
__device__ __half g_hp  [(size_t)MAX_N * D];       // (x @ W^T) * dis[row], fp16

// ---------------------------------------------------------------------------
// 1. prep: zero counters + detect edge dtype + convert W to fp16
// ---------------------------------------------------------------------------
__global__ void prep_kernel(const float* __restrict__ w, const int* __restrict__ p, int n) {
    int gid = blockIdx.x * blockDim.x + threadIdx.x;
    if (gid < n) g_cnt[gid] = 0;
    if (gid == 0) g_spillcnt = 0;
    if (gid < D * D / 2) {
        float2 v = ((const float2*)w)[gid];
        ((__half2*)g_wh)[gid] = __floats2half2_rn(v.x, v.y);
    }
    if (blockIdx.x == 0) {
        __shared__ int any;
        if (threadIdx.x == 0) any = 0;
        __syncthreads();
        int v = 0;
        for (int i = threadIdx.x; i < 2048; i += blockDim.x) v |= p[2 * i + 1];
        if (v) atomicOr(&any, 1);
        __syncthreads();
        if (threadIdx.x == 0) g_is64 = (any == 0) ? 1 : 0;
    }
}

// ---------------------------------------------------------------------------
// 2. fill: single edge pass builds binned adjacency + degree counts
// ---------------------------------------------------------------------------
__device__ __forceinline__ void fill_one(int s, int d, int n) {
    if ((unsigned)d < (unsigned)n) {
        if ((unsigned)s >= (unsigned)n) s = 0;
        int pos = atomicAdd(&g_cnt[d], 1);
        if (pos < BINSZ) {
            g_bins[(size_t)d * BINSZ + pos] = s;
        } else {
            int sp = atomicAdd(&g_spillcnt, 1);
            if (sp < MAX_SPILL) g_spill[sp] = make_int2(s, d);
        }
    }
}

__global__ void fill_kernel(const int* __restrict__ p, int e, int n) {
    int gid = blockIdx.x * blockDim.x + threadIdx.x;
    int stride = gridDim.x * blockDim.x;
    if (!g_is64) {
        const int4* s4 = (const int4*)p;
        const int4* d4 = (const int4*)(p + e);
        int e4 = e >> 2;
        for (int i = gid; i < e4; i += stride) {
            int4 sv = s4[i];
            int4 dv = d4[i];
            fill_one(sv.x, dv.x, n);
            fill_one(sv.y, dv.y, n);
            fill_one(sv.z, dv.z, n);
            fill_one(sv.w, dv.w, n);
        }
        if (gid < (e & 3)) {
            int i = (e & ~3) + gid;
            fill_one(p[i], p[(size_t)e + i], n);
        }
    } else {
        for (int i = gid; i < e; i += stride) {
            int s = p[2 * (size_t)i];
            int d = p[2 * ((size_t)e + i)];
            fill_one(s, d, n);
        }
    }
}

// ---------------------------------------------------------------------------
// 3. dis = rsqrt(deg + 1)
// ---------------------------------------------------------------------------
__global__ void dis_kernel(int n) {
    int i = blockIdx.x * blockDim.x + threadIdx.x;
    if (i < n) g_dis[i] = rsqrtf((float)(g_cnt[i] + 1));
}

// ---------------------------------------------------------------------------
// 4. tensor-core GEMM, B-in-registers + persistent row groups.
//    Block: 256 thr (8 warps), 256 rows (8 groups x 32). Warp w:
//    rows 16*(w&1)+.., cols 32*(w>>1)+.. ; B frags resident (64 regs/warp).
// ---------------------------------------------------------------------------
__global__ __launch_bounds__(256, 2) void gemm_mma_kernel(
    const float* __restrict__ x, int n)
{
    __shared__ __half sw[D][136];          // W staged once per block
    __shared__ __half sx[2][BM][136];      // double-buffered x tiles

    const int t = threadIdx.x;
    const int wid = t >> 5, lane = t & 31;
    const int blockRow0 = blockIdx.x * (BM * GROUPS);

    // stage W (each thread: one half-row segment of 64 cols = 8 uint4)
    {
        int r = t >> 1, cseg = (t & 1) * 64;
        const uint4* wp = (const uint4*)(g_wh + r * D + cseg);
#pragma unroll
        for (int q = 0; q < 8; q++)
            *(uint4*)&sw[r][cseg + 8 * q] = wp[q];
    }
    __syncthreads();

    const int mrow0 = (wid & 1) * 16;
    const int ncol0 = (wid >> 1) * 32;
    const int brow = lane & 7;
    const int bcol = ((lane >> 3) & 1) * 8;
    const int arow = mrow0 + (lane & 15);
    const int acol = (lane >> 4) * 8;

    // load all B fragments into registers: 8 k-chunks x 4 n-tiles x 2 regs
    uint32_t bf[8][4][2];
#pragma unroll
    for (int k0 = 0; k0 < 8; k0++) {
#pragma unroll
        for (int nt = 0; nt < 4; nt++) {
            unsigned baddr = (unsigned)__cvta_generic_to_shared(
                &sw[ncol0 + nt * 8 + brow][k0 * 16 + bcol]);
            asm volatile("ldmatrix.sync.aligned.m8n8.x2.shared.b16 {%0,%1}, [%2];"
                         : "=r"(bf[k0][nt][0]), "=r"(bf[k0][nt][1]) : "r"(baddr));
        }
    }

    // per-thread x staging: row r, 16-col segment
    const int sr = t >> 3, scseg = (t & 7) * 16;

    // prologue: load group 0 into registers
    float4 xv[4];
    {
        int gr = blockRow0 + sr;
        const float4* xp = (const float4*)(x + (size_t)gr * D + scseg);
#pragma unroll
        for (int q = 0; q < 4; q++)
            xv[q] = (gr < n) ? xp[q] : make_float4(0.f, 0.f, 0.f, 0.f);
    }

    __half2* hp2 = (__half2*)g_hp;

    for (int g = 0; g < GROUPS; g++) {
        const int buf = g & 1;
        const int row0 = blockRow0 + g * BM;
        if (row0 >= n) break;

        // convert + store prefetched registers into smem buffer
#pragma unroll
        for (int q = 0; q < 4; q++) {
            *(__half2*)&sx[buf][sr][scseg + 4 * q]     = __floats2half2_rn(xv[q].x, xv[q].y);
            *(__half2*)&sx[buf][sr][scseg + 4 * q + 2] = __floats2half2_rn(xv[q].z, xv[q].w);
        }
        __syncthreads();

        // prefetch next group (overlaps with MMAs below)
        if (g + 1 < GROUPS) {
            int gr = blockRow0 + (g + 1) * BM + sr;
            const float4* xp = (const float4*)(x + (size_t)gr * D + scseg);
#pragma unroll
            for (int q = 0; q < 4; q++)
                xv[q] = (gr < n) ? xp[q] : make_float4(0.f, 0.f, 0.f, 0.f);
        }

        // compute: 8 A-ldmatrix, 32 MMAs
        float acc[4][4];
#pragma unroll
        for (int i = 0; i < 4; i++) { acc[i][0]=0.f; acc[i][1]=0.f; acc[i][2]=0.f; acc[i][3]=0.f; }

#pragma unroll
        for (int k0 = 0; k0 < 8; k0++) {
            unsigned aaddr = (unsigned)__cvta_generic_to_shared(
                &sx[buf][arow][k0 * 16 + acol]);
            uint32_t a0, a1, a2, a3;
            asm volatile("ldmatrix.sync.aligned.m8n8.x4.shared.b16 {%0,%1,%2,%3}, [%4];"
                         : "=r"(a0), "=r"(a1), "=r"(a2), "=r"(a3) : "r"(aaddr));
#pragma unroll
            for (int nt = 0; nt < 4; nt++) {
                asm volatile("mma.sync.aligned.m16n8k16.row.col.f32.f16.f16.f32 "
                             "{%0,%1,%2,%3}, {%4,%5,%6,%7}, {%8,%9}, {%0,%1,%2,%3};"
                             : "+f"(acc[nt][0]), "+f"(acc[nt][1]),
                               "+f"(acc[nt][2]), "+f"(acc[nt][3])
                             : "r"(a0), "r"(a1), "r"(a2), "r"(a3),
                               "r"(bf[k0][nt][0]), "r"(bf[k0][nt][1]));
            }
        }

        // epilogue: scale by dis[row], convert to fp16, store
        const int gq = lane >> 2, tid4 = lane & 3;
        const int r0 = row0 + mrow0 + gq;
        const int r1 = r0 + 8;
        float s0 = (r0 < n) ? g_dis[r0] : 0.f;
        float s1 = (r1 < n) ? g_dis[r1] : 0.f;
#pragma unroll
        for (int nt = 0; nt < 4; nt++) {
            int c = ncol0 + nt * 8 + 2 * tid4;
            if (r0 < n) hp2[(size_t)r0 * 64 + (c >> 1)] = __floats2half2_rn(acc[nt][0] * s0, acc[nt][1] * s0);
            if (r1 < n) hp2[(size_t)r1 * 64 + (c >> 1)] = __floats2half2_rn(acc[nt][2] * s1, acc[nt][3] * s1);
        }
        // no trailing sync needed: next iteration's store targets the other
        // buffer; the sync at the top of the next iteration orders buffer reuse.
    }
}

// ---------------------------------------------------------------------------
// 5. gather-aggregate: one warp per node, two edges per iteration.
// ---------------------------------------------------------------------------
__device__ __forceinline__ void add8(float* a, uint4 v) {
    float2 f;
    f = __half22float2(*(__half2*)&v.x); a[0] += f.x; a[1] += f.y;
    f = __half22float2(*(__half2*)&v.y); a[2] += f.x; a[3] += f.y;
    f = __half22float2(*(__half2*)&v.z); a[4] += f.x; a[5] += f.y;
    f = __half22float2(*(__half2*)&v.w); a[6] += f.x; a[7] += f.y;
}

__global__ __launch_bounds__(256) void aggregate_kernel(
    const float* __restrict__ bias, float* __restrict__ out, int n)
{
    int node = (blockIdx.x * blockDim.x + threadIdx.x) >> 5;
    int lane = threadIdx.x & 31;
    if (node >= n) return;
    const int half_id = lane >> 4;
    const int sub = lane & 15;

    const uint4* hp16 = (const uint4*)g_hp;
    const int start = node * BINSZ;
    int k = g_cnt[node];
    if (k > BINSZ) k = BINSZ;

    float acc[8] = {0.f, 0.f, 0.f, 0.f, 0.f, 0.f, 0.f, 0.f};
    if (half_id == 0) add8(acc, hp16[(size_t)node * 16 + sub]);   // self loop

    int j = 0;
    int full = k & ~31;
    for (; j < full; j += 32) {
        int my = g_bins[start + j + lane];
#pragma unroll
        for (int t2 = 0; t2 < 16; t2++) {
            int s = __shfl_sync(0xFFFFFFFFu, my, 2 * t2 + half_id);
            add8(acc, hp16[(size_t)s * 16 + sub]);
        }
    }
    int m = k - j;
    if (m > 0) {
        int idx = j + lane;
        int my = (idx < k) ? g_bins[start + idx] : 0;
        int pairs = m >> 1;
        for (int t2 = 0; t2 < pairs; t2++) {
            int s = __shfl_sync(0xFFFFFFFFu, my, 2 * t2 + half_id);
            add8(acc, hp16[(size_t)s * 16 + sub]);
        }
        if (m & 1) {
            int s = __shfl_sync(0xFFFFFFFFu, my, m - 1);
            if (half_id == 0) add8(acc, hp16[(size_t)s * 16 + sub]);
        }
    }

#pragma unroll
    for (int i = 0; i < 8; i++)
        acc[i] += __shfl_down_sync(0xFFFFFFFFu, acc[i], 16);

    if (half_id == 0) {
        float sd = g_dis[node];
        const float4* b4 = (const float4*)bias;
        float4 ba = b4[sub * 2], bb = b4[sub * 2 + 1];
        float4 o0, o1;
        o0.x = fmaf(sd, acc[0], ba.x);
        o0.y = fmaf(sd, acc[1], ba.y);
        o0.z = fmaf(sd, acc[2], ba.z);
        o0.w = fmaf(sd, acc[3], ba.w);
        o1.x = fmaf(sd, acc[4], bb.x);
        o1.y = fmaf(sd, acc[5], bb.y);
        o1.z = fmaf(sd, acc[6], bb.z);
        o1.w = fmaf(sd, acc[7], bb.w);
        float4* op = (float4*)out + (size_t)node * 32 + sub * 2;
        op[0] = o0;
        op[1] = o1;
    }
}

// ---------------------------------------------------------------------------
// 6. spill fixup (normally zero work)
// ---------------------------------------------------------------------------
__global__ void spill_kernel(float* __restrict__ out) {
    int nsp = g_spillcnt;
    if (nsp > MAX_SPILL) nsp = MAX_SPILL;
    int warp = (blockIdx.x * blockDim.x + threadIdx.x) >> 5;
    int lane = threadIdx.x & 31;
    int wstride = (gridDim.x * blockDim.x) >> 5;
    for (int i = warp; i < nsp; i += wstride) {
        int2 ed = g_spill[i];
        float sd = g_dis[ed.y];
        uint2 v = ((const uint2*)g_hp)[(size_t)ed.x * 32 + lane];
        float2 f0 = __half22float2(*(__half2*)&v.x);
        float2 f1 = __half22float2(*(__half2*)&v.y);
        float* o = out + (size_t)ed.y * D + lane * 4;
        atomicAdd(o + 0, sd * f0.x);
        atomicAdd(o + 1, sd * f0.y);
        atomicAdd(o + 2, sd * f1.x);
        atomicAdd(o + 3, sd * f1.y);
    }
}

// ---------------------------------------------------------------------------
// 7. zero any padding tail of d_out
// ---------------------------------------------------------------------------
__global__ void zero_tail_kernel(float* out, int begin, int end) {
    int i = begin + blockIdx.x * blockDim.x + threadIdx.x;
    if (i < end) out[i] = 0.f;
}

// ---------------------------------------------------------------------------
extern "C" void kernel_launch(void* const* d_in, const int* in_sizes, int n_in,
                              void* d_out, int out_size) {
    const float* x    = (const float*)d_in[0];
    const int*   ei   = (const int*)d_in[1];
    const float* w    = (const float*)d_in[2];
    const float* bias = (const float*)d_in[3];
    float*       out  = (float*)d_out;

    const int n = in_sizes[0] / D;     // 100000
    const int e = in_sizes[1] / 2;     // 3200000

    // 1. zero counters + dtype detect + W conversion (fused)
    prep_kernel<<<(n + 255) / 256, 256>>>(w, ei, n);

    // 2. single edge pass: binned adjacency + degrees
    fill_kernel<<<2048, 256>>>(ei, e, n);

    // 3. dis = rsqrt(deg + 1)
    dis_kernel<<<(n + 255) / 256, 256>>>(n);

    // 4. tensor-core dense transform (256 rows per block)
    {
        int rows_per_block = BM * GROUPS;
        gemm_mma_kernel<<<(n + rows_per_block - 1) / rows_per_block, 256>>>(x, n);
    }

    // 5. gather aggregation with fused finalize
    {
        long long total_threads = (long long)n * 32;
        int blocks = (int)((total_threads + 255) / 256);
        aggregate_kernel<<<blocks, 256>>>(bias, out, n);
    }

    // 6. spill fixup (no-op unless a node exceeded BINSZ)
    spill_kernel<<<64, 256>>>(out);

    // 7. padding tail, if any
    if (out_size > n * D) {
        int extra = out_size - n * D;
        zero_tail_kernel<<<(extra + 255) / 256, 256>>>(out, n * D, out_size);
    }
}